// round 1
// baseline (speedup 1.0000x reference)
#include <cuda_runtime.h>
#include <cstdint>

#define NIMG  8
#define NPROP 8000
#define NCLS  80
#define NLOG  81
#define KTOP  2048
#define CAP   16384
#define NDET  100
#define NW    32   // 2048 / 64 bits

#define SCORE_THRE 0.15f
#define MIN_AREA   0.1f
#define NMS_TH     0.5f

// ---------------- scratch (device globals; no allocations allowed) ----------
__device__ int                 g_cnt[NIMG];
__device__ unsigned long long  g_keys[NIMG][CAP];
__device__ float               g_box[NIMG][KTOP][4];
__device__ float               g_val[NIMG][KTOP];
__device__ int                 g_lab[NIMG][KTOP];
__device__ unsigned int        g_maxc[NIMG];                 // float bits (>=0)
__device__ unsigned long long  g_sup[NIMG][KTOP][NW];

// ---------------- kernel 1: reset counters / key pad ------------------------
__global__ void init_kernel() {
    int tid = blockIdx.x * blockDim.x + threadIdx.x;
    if (tid < NIMG) { g_cnt[tid] = 0; g_maxc[tid] = 0u; }
    unsigned long long* k = &g_keys[0][0];
    for (int i = tid; i < NIMG * CAP; i += gridDim.x * blockDim.x)
        k[i] = 0ull;
}

// ---------------- kernel 2: softmax + decode + filter + append --------------
// one warp per proposal; exp values computed once and reused for sum + scores
__global__ void score_kernel(const float* __restrict__ logits,
                             const float* __restrict__ deltas,
                             const float* __restrict__ props) {
    int b    = blockIdx.y;
    int p    = blockIdx.x * (blockDim.x >> 5) + (threadIdx.x >> 5);
    int lane = threadIdx.x & 31;
    if (p >= NPROP) return;

    const float* lg = logits + (size_t)(b * NPROP + p) * NLOG;
    float v0 = lg[lane];
    float v1 = lg[32 + lane];
    float v2 = (lane < NLOG - 64) ? lg[64 + lane] : -3.4e38f;

    float mx = fmaxf(fmaxf(v0, v1), v2);
#pragma unroll
    for (int o = 16; o; o >>= 1) mx = fmaxf(mx, __shfl_xor_sync(0xffffffffu, mx, o));

    float e0 = expf(v0 - mx);
    float e1 = expf(v1 - mx);
    float e2 = (lane < NLOG - 64) ? expf(v2 - mx) : 0.0f;
    float s  = e0 + e1 + e2;
#pragma unroll
    for (int o = 16; o; o >>= 1) s += __shfl_xor_sync(0xffffffffu, s, o);

    // anchors
    const float* pr = props + (size_t)(b * NPROP + p) * 4;
    float ax0 = pr[0], ay0 = pr[1], ax1 = pr[2], ay1 = pr[3];
    float wa  = ax1 - ax0, ha = ay1 - ay0;
    float cxa = ax0 + 0.5f * wa, cya = ay0 + 0.5f * ha;

    const float* dl = deltas + (size_t)(b * NPROP + p) * (4 * NLOG);

    float es[3] = { e0, e1, e2 };
#pragma unroll
    for (int t = 0; t < 3; t++) {
        int cls = lane + 32 * t;                 // softmax class index
        if (cls >= 1 && cls < NLOG) {
            float sc = es[t] / s;
            if (sc > SCORE_THRE) {
                // deltas[:,4:] row (p*C + (cls-1)) -> columns [4*cls, 4*cls+4)
                float dx = dl[4 * cls + 0];
                float dy = dl[4 * cls + 1];
                float dw = dl[4 * cls + 2];
                float dh = dl[4 * cls + 3];
                float cx = dx * wa + cxa;
                float cy = dy * ha + cya;
                float w  = expf(dw) * wa;
                float h  = expf(dh) * ha;
                float bx0 = cx - 0.5f * w, by0 = cy - 0.5f * h;
                float bx1 = cx + 0.5f * w, by1 = cy + 0.5f * h;
                float area = (by1 - by0) * (bx1 - bx0);
                if (area > MIN_AREA) {
                    int idx = p * NCLS + (cls - 1);
                    int pos = atomicAdd(&g_cnt[b], 1);
                    if (pos < CAP) {
                        unsigned long long key =
                            ((unsigned long long)__float_as_uint(sc) << 32) |
                            (unsigned)(0xFFFFFFFFu - (unsigned)idx);
                        g_keys[b][pos] = key;
                    }
                }
            }
        }
    }
}

// ---------------- kernel 3: per-image bitonic sort of 16384 keys ------------
__global__ void sort_kernel() {
    extern __shared__ unsigned long long sk[];
    int b = blockIdx.x;
    int t = threadIdx.x;
    for (int i = t; i < CAP; i += blockDim.x) sk[i] = g_keys[b][i];
    __syncthreads();

    for (int k = 2; k <= CAP; k <<= 1) {
        for (int j = k >> 1; j; j >>= 1) {
            for (int i = t; i < CAP; i += blockDim.x) {
                int ixj = i ^ j;
                if (ixj > i) {
                    unsigned long long a = sk[i], c = sk[ixj];
                    bool up = ((i & k) == 0);      // ascending overall
                    if ((a > c) == up) { sk[i] = c; sk[ixj] = a; }
                }
            }
            __syncthreads();
        }
    }
    // write top KTOP keys, descending
    for (int r = t; r < KTOP; r += blockDim.x)
        g_keys[b][r] = sk[CAP - 1 - r];
}

// ---------------- kernel 4: gather top-2048, re-decode, max_coord -----------
__global__ void gather_kernel(const float* __restrict__ deltas,
                              const float* __restrict__ props) {
    int b = blockIdx.y;
    int r = blockIdx.x * blockDim.x + threadIdx.x;
    if (r >= KTOP) return;

    unsigned long long key = g_keys[b][r];
    if (key == 0ull) {                       // padded slot
        g_val[b][r] = -1.0f;
        g_lab[b][r] = 0;
        g_box[b][r][0] = 0.f; g_box[b][r][1] = 0.f;
        g_box[b][r][2] = 0.f; g_box[b][r][3] = 0.f;
        return;
    }
    float    sc  = __uint_as_float((unsigned)(key >> 32));
    unsigned idx = 0xFFFFFFFFu - (unsigned)(key & 0xFFFFFFFFull);
    int p   = (int)(idx / NCLS);
    int j   = (int)(idx - (unsigned)p * NCLS);
    int cls = j + 1;

    const float* pr = props + (size_t)(b * NPROP + p) * 4;
    float ax0 = pr[0], ay0 = pr[1], ax1 = pr[2], ay1 = pr[3];
    float wa  = ax1 - ax0, ha = ay1 - ay0;
    float cxa = ax0 + 0.5f * wa, cya = ay0 + 0.5f * ha;

    const float* dl = deltas + (size_t)(b * NPROP + p) * (4 * NLOG);
    float dx = dl[4 * cls + 0];
    float dy = dl[4 * cls + 1];
    float dw = dl[4 * cls + 2];
    float dh = dl[4 * cls + 3];
    float cx = dx * wa + cxa;
    float cy = dy * ha + cya;
    float w  = expf(dw) * wa;
    float h  = expf(dh) * ha;
    float bx0 = cx - 0.5f * w, by0 = cy - 0.5f * h;
    float bx1 = cx + 0.5f * w, by1 = cy + 0.5f * h;

    g_box[b][r][0] = bx0; g_box[b][r][1] = by0;
    g_box[b][r][2] = bx1; g_box[b][r][3] = by1;
    g_val[b][r] = sc;
    g_lab[b][r] = cls;

    // max over where(cv, cb, 0) == max(0, max over coords)
    float m = fmaxf(fmaxf(bx0, bx1), fmaxf(by0, by1));
    m = fmaxf(m, 0.0f);
    atomicMax(&g_maxc[b], __float_as_uint(m));   // float bits monotone for >=0
}

// ---------------- kernel 5: suppression bitmask (2048x2048 IoU) -------------
// block = 32 warps = 32 rows; boxes staged in smem (stride 5, conflict-free)
__global__ void sup_kernel() {
    __shared__ float sob[KTOP * 5];   // x0,y0,x1,y1,area per entry (40 KB)
    int b  = blockIdx.y;
    float mc = __uint_as_float(g_maxc[b]) + 1.0f;

    for (int i = threadIdx.x; i < KTOP; i += blockDim.x) {
        float off = (float)g_lab[b][i] * mc;
        float x0 = g_box[b][i][0] + off;
        float y0 = g_box[b][i][1] + off;
        float x1 = g_box[b][i][2] + off;
        float y1 = g_box[b][i][3] + off;
        sob[i * 5 + 0] = x0;
        sob[i * 5 + 1] = y0;
        sob[i * 5 + 2] = x1;
        sob[i * 5 + 3] = y1;
        sob[i * 5 + 4] = (x1 - x0) * (y1 - y0);
    }
    __syncthreads();

    int warp = threadIdx.x >> 5;
    int lane = threadIdx.x & 31;
    int i = blockIdx.x * 32 + warp;

    float ax0 = sob[i * 5 + 0], ay0 = sob[i * 5 + 1];
    float ax1 = sob[i * 5 + 2], ay1 = sob[i * 5 + 3];
    float aar = sob[i * 5 + 4];

    unsigned long long myw = 0ull;
#pragma unroll 4
    for (int t = 0; t < 64; t++) {
        int j = t * 32 + lane;
        bool hit = false;
        if (j > i) {
            float lx = fmaxf(ax0, sob[j * 5 + 0]);
            float ly = fmaxf(ay0, sob[j * 5 + 1]);
            float rx = fminf(ax1, sob[j * 5 + 2]);
            float ry = fminf(ay1, sob[j * 5 + 3]);
            float iw = fmaxf(rx - lx, 0.0f);
            float ih = fmaxf(ry - ly, 0.0f);
            float inter = iw * ih;
            float iou = inter / (aar + sob[j * 5 + 4] - inter + 1e-9f);
            hit = iou > NMS_TH;
        }
        unsigned bal = __ballot_sync(0xffffffffu, hit);
        if (lane == (t >> 1))
            myw |= ((unsigned long long)bal) << ((t & 1) * 32);
    }
    g_sup[b][i][lane] = myw;
}

// ---------------- kernel 6: greedy NMS scan + final top-100 + output --------
// one 32-lane warp per image; lane L holds removal-bitmask word L
__global__ void scan_kernel(float* __restrict__ out) {
    int b    = blockIdx.x;
    int lane = threadIdx.x;

    unsigned long long remv = 0ull;
#pragma unroll 8
    for (int t = 0; t < 64; t++)
        if (g_val[b][lane * 64 + t] <= 0.0f) remv |= (1ull << t);   // cv == false

    __shared__ int kept[NDET];
    int cnt = 0;
    for (int i = 0; i < KTOP && cnt < NDET; i++) {
        unsigned long long rw = __shfl_sync(0xffffffffu, remv, i >> 6);
        if (!((rw >> (i & 63)) & 1ull)) {
            if (lane == 0) kept[cnt] = i;
            cnt++;
            remv |= g_sup[b][i][lane];
        }
    }
    __syncwarp();

    for (int s = lane; s < NDET; s += 32) {
        float b0 = 0.f, b1 = 0.f, b2 = 0.f, b3 = 0.f, sv = 0.f, lv = 0.f;
        if (s < cnt) {
            int i = kept[s];
            b0 = g_box[b][i][0]; b1 = g_box[b][i][1];
            b2 = g_box[b][i][2]; b3 = g_box[b][i][3];
            sv = g_val[b][i];
            lv = (float)g_lab[b][i];
        }
        float* ob = out + (size_t)b * NDET * 4 + s * 4;
        ob[0] = b0; ob[1] = b1; ob[2] = b2; ob[3] = b3;
        out[NIMG * NDET * 4 + b * NDET + s] = sv;           // scores block
        out[NIMG * NDET * 5 + b * NDET + s] = lv;           // labels block
    }
}

// ---------------- launcher ---------------------------------------------------
extern "C" void kernel_launch(void* const* d_in, const int* in_sizes, int n_in,
                              void* d_out, int out_size) {
    const float* logits = (const float*)d_in[0];   // [8,8000,81]
    const float* deltas = (const float*)d_in[1];   // [8,8000,324]
    const float* props  = (const float*)d_in[2];   // [8,8000,4]
    float* out = (float*)d_out;                    // [boxes|scores|labels] f32

    cudaFuncSetAttribute(sort_kernel,
                         cudaFuncAttributeMaxDynamicSharedMemorySize,
                         CAP * (int)sizeof(unsigned long long));

    init_kernel<<<256, 256>>>();
    score_kernel<<<dim3(NPROP / 8, NIMG), 256>>>(logits, deltas, props);
    sort_kernel<<<NIMG, 1024, CAP * sizeof(unsigned long long)>>>();
    gather_kernel<<<dim3(KTOP / 256, NIMG), 256>>>(deltas, props);
    sup_kernel<<<dim3(KTOP / 32, NIMG), 1024>>>();
    scan_kernel<<<NIMG, 32>>>(out);
}

// round 3
// speedup vs baseline: 2.4447x; 2.4447x over previous
#include <cuda_runtime.h>
#include <cstdint>

#define NIMG  8
#define NPROP 8000
#define NCLS  80
#define NLOG  81
#define KTOP  2048
#define CAP   4096
#define NDET  100
#define NW    32   // 2048 / 64 bits
#define PRE   160  // suppression rows preloaded into smem in scan

#define SCORE_THRE 0.15f
#define MIN_AREA   0.1f
#define NMS_TH     0.5f

// ---------------- scratch (device globals; no allocations allowed) ----------
__device__ int                 g_cnt[NIMG];
__device__ unsigned long long  g_keys[NIMG][CAP];
__device__ float               g_box[NIMG][KTOP][4];
__device__ float               g_val[NIMG][KTOP];
__device__ int                 g_lab[NIMG][KTOP];
__device__ unsigned int        g_maxc[NIMG];                 // float bits (>=0)
__device__ unsigned long long  g_sup[NIMG][KTOP][NW];

// ---------------- kernel 1: softmax + decode + filter + append --------------
// one warp per proposal; accurate expf (rank-stability vs reference);
// single IEEE reciprocal per warp instead of per-lane divides
__global__ void score_kernel(const float* __restrict__ logits,
                             const float* __restrict__ deltas,
                             const float* __restrict__ props) {
    int b    = blockIdx.y;
    int p    = blockIdx.x * (blockDim.x >> 5) + (threadIdx.x >> 5);
    int lane = threadIdx.x & 31;
    if (p >= NPROP) return;

    const float* lg = logits + (size_t)(b * NPROP + p) * NLOG;
    float v0 = lg[lane];
    float v1 = lg[32 + lane];
    float v2 = (lane < NLOG - 64) ? lg[64 + lane] : -3.4e38f;

    float mx = fmaxf(fmaxf(v0, v1), v2);
#pragma unroll
    for (int o = 16; o; o >>= 1) mx = fmaxf(mx, __shfl_xor_sync(0xffffffffu, mx, o));

    float e0 = expf(v0 - mx);
    float e1 = expf(v1 - mx);
    float e2 = (lane < NLOG - 64) ? expf(v2 - mx) : 0.0f;
    float s  = e0 + e1 + e2;
#pragma unroll
    for (int o = 16; o; o >>= 1) s += __shfl_xor_sync(0xffffffffu, s, o);

    float inv_s = (lane == 0) ? (1.0f / s) : 0.0f;   // one IEEE rcp per warp
    inv_s = __shfl_sync(0xffffffffu, inv_s, 0);

    // anchors
    const float* pr = props + (size_t)(b * NPROP + p) * 4;
    float ax0 = pr[0], ay0 = pr[1], ax1 = pr[2], ay1 = pr[3];
    float wa  = ax1 - ax0, ha = ay1 - ay0;
    float cxa = ax0 + 0.5f * wa, cya = ay0 + 0.5f * ha;

    const float* dl = deltas + (size_t)(b * NPROP + p) * (4 * NLOG);

    float es[3] = { e0, e1, e2 };
#pragma unroll
    for (int t = 0; t < 3; t++) {
        int cls = lane + 32 * t;                 // softmax class index
        if (cls >= 1 && cls < NLOG) {
            float sc = es[t] * inv_s;
            if (sc > SCORE_THRE) {
                float dx = dl[4 * cls + 0];
                float dy = dl[4 * cls + 1];
                float dw = dl[4 * cls + 2];
                float dh = dl[4 * cls + 3];
                float w  = __expf(dw) * wa;      // output-coord only; 2e-7 rel ok
                float h  = __expf(dh) * ha;
                float area = h * w;              // (by1-by0)*(bx1-bx0) == h*w
                (void)dx; (void)dy;
                if (area > MIN_AREA) {
                    int idx = p * NCLS + (cls - 1);
                    int pos = atomicAdd(&g_cnt[b], 1);
                    if (pos < CAP) {
                        unsigned long long key =
                            ((unsigned long long)__float_as_uint(sc) << 32) |
                            (unsigned)(0xFFFFFFFFu - (unsigned)idx);
                        g_keys[b][pos] = key;
                    }
                }
            }
        }
    }
}

// ---------------- kernel 2: per-image bitonic sort, dynamic size ------------
__global__ void sort_kernel() {
    __shared__ unsigned long long sk[CAP];
    int b = blockIdx.x;
    int t = threadIdx.x;
    int cnt = g_cnt[b];
    if (cnt > CAP) cnt = CAP;

    int npow = 1024;
    while (npow < cnt) npow <<= 1;               // <= CAP

    for (int i = t; i < npow; i += 1024)
        sk[i] = (i < cnt) ? g_keys[b][i] : 0ull;
    __syncthreads();
    if (t == 0) g_cnt[b] = 0;                    // reset for next replay

    for (int k = 2; k <= npow; k <<= 1) {
        for (int j = k >> 1; j; j >>= 1) {
            for (int idx = t; idx < (npow >> 1); idx += 1024) {
                int low = idx & (j - 1);
                int i   = ((idx ^ low) << 1) | low;    // insert 0 bit at log2(j)
                int ixj = i | j;
                unsigned long long a = sk[i], c = sk[ixj];
                bool up = ((i & k) == 0);              // ascending overall
                if ((a > c) == up) { sk[i] = c; sk[ixj] = a; }
            }
            __syncthreads();
        }
    }
    // write top KTOP keys, descending
    for (int r = t; r < KTOP; r += 1024)
        g_keys[b][r] = (r < npow) ? sk[npow - 1 - r] : 0ull;
}

// ---------------- kernel 3: gather top-2048, re-decode, max_coord -----------
__global__ void gather_kernel(const float* __restrict__ deltas,
                              const float* __restrict__ props) {
    int b = blockIdx.y;
    int r = blockIdx.x * blockDim.x + threadIdx.x;
    if (r >= KTOP) return;

    unsigned long long key = g_keys[b][r];
    if (key == 0ull) {                       // padded slot
        g_val[b][r] = -1.0f;
        g_lab[b][r] = 0;
        g_box[b][r][0] = 0.f; g_box[b][r][1] = 0.f;
        g_box[b][r][2] = 0.f; g_box[b][r][3] = 0.f;
        return;
    }
    float    sc  = __uint_as_float((unsigned)(key >> 32));
    unsigned idx = 0xFFFFFFFFu - (unsigned)(key & 0xFFFFFFFFull);
    int p   = (int)(idx / NCLS);
    int j   = (int)(idx - (unsigned)p * NCLS);
    int cls = j + 1;

    const float* pr = props + (size_t)(b * NPROP + p) * 4;
    float ax0 = pr[0], ay0 = pr[1], ax1 = pr[2], ay1 = pr[3];
    float wa  = ax1 - ax0, ha = ay1 - ay0;
    float cxa = ax0 + 0.5f * wa, cya = ay0 + 0.5f * ha;

    const float* dl = deltas + (size_t)(b * NPROP + p) * (4 * NLOG);
    float dx = dl[4 * cls + 0];
    float dy = dl[4 * cls + 1];
    float dw = dl[4 * cls + 2];
    float dh = dl[4 * cls + 3];
    float cx = dx * wa + cxa;
    float cy = dy * ha + cya;
    float w  = expf(dw) * wa;
    float h  = expf(dh) * ha;
    float bx0 = cx - 0.5f * w, by0 = cy - 0.5f * h;
    float bx1 = cx + 0.5f * w, by1 = cy + 0.5f * h;

    g_box[b][r][0] = bx0; g_box[b][r][1] = by0;
    g_box[b][r][2] = bx1; g_box[b][r][3] = by1;
    g_val[b][r] = sc;
    g_lab[b][r] = cls;

    // max over where(cv, cb, 0) == max(0, max over coords)
    float m = fmaxf(fmaxf(bx0, bx1), fmaxf(by0, by1));
    m = fmaxf(m, 0.0f);
    atomicMax(&g_maxc[b], __float_as_uint(m));   // float bits monotone for >=0
}

// ---------------- kernel 4: suppression bitmask (upper-tri IoU) -------------
__global__ void sup_kernel() {
    __shared__ float sob[KTOP * 5];   // x0,y0,x1,y1,area per entry (40 KB)
    int b  = blockIdx.y;
    float mc = __uint_as_float(g_maxc[b]) + 1.0f;

    for (int i = threadIdx.x; i < KTOP; i += blockDim.x) {
        float off = (float)g_lab[b][i] * mc;
        float x0 = g_box[b][i][0] + off;
        float y0 = g_box[b][i][1] + off;
        float x1 = g_box[b][i][2] + off;
        float y1 = g_box[b][i][3] + off;
        sob[i * 5 + 0] = x0;
        sob[i * 5 + 1] = y0;
        sob[i * 5 + 2] = x1;
        sob[i * 5 + 3] = y1;
        sob[i * 5 + 4] = (x1 - x0) * (y1 - y0);
    }
    __syncthreads();

    int warp = threadIdx.x >> 5;
    int lane = threadIdx.x & 31;
    int i = blockIdx.x * 32 + warp;

    float ax0 = sob[i * 5 + 0], ay0 = sob[i * 5 + 1];
    float ax1 = sob[i * 5 + 2], ay1 = sob[i * 5 + 3];
    float aar = sob[i * 5 + 4];

    unsigned long long myw = 0ull;
    // only j > i can suppress; words below i>>6 stay 0
    for (int t = (i >> 5); t < 64; t++) {
        int j = t * 32 + lane;
        bool hit = false;
        if (j > i) {
            float lx = fmaxf(ax0, sob[j * 5 + 0]);
            float ly = fmaxf(ay0, sob[j * 5 + 1]);
            float rx = fminf(ax1, sob[j * 5 + 2]);
            float ry = fminf(ay1, sob[j * 5 + 3]);
            float iw = fmaxf(rx - lx, 0.0f);
            float ih = fmaxf(ry - ly, 0.0f);
            float inter = iw * ih;
            float iou = inter / (aar + sob[j * 5 + 4] - inter + 1e-9f);
            hit = iou > NMS_TH;
        }
        unsigned bal = __ballot_sync(0xffffffffu, hit);
        if (lane == (t >> 1))
            myw |= ((unsigned long long)bal) << ((t & 1) * 32);
    }
    g_sup[b][i][lane] = myw;
}

// ---------------- kernel 5: greedy NMS skip-scan (smem) + output ------------
// 256 threads/image: 8 warps preload, warp 0 runs the serial chain on smem
__global__ void scan_kernel(float* __restrict__ out) {
    __shared__ unsigned long long ssup[PRE][NW];   // 40 KB
    __shared__ unsigned long long s_remv[NW];
    __shared__ int kept[NDET];
    __shared__ int s_cnt;
    int b    = blockIdx.x;
    int tid  = threadIdx.x;
    int warp = tid >> 5;
    int lane = tid & 31;

    // cv removal words via ballots (8 warps x 4 words)
    for (int wd = warp; wd < NW; wd += 8) {
        unsigned lo = __ballot_sync(0xffffffffu, g_val[b][wd * 64 + lane]      <= 0.0f);
        unsigned hi = __ballot_sync(0xffffffffu, g_val[b][wd * 64 + 32 + lane] <= 0.0f);
        if (lane == 0)
            s_remv[wd] = (unsigned long long)lo | ((unsigned long long)hi << 32);
    }
    // preload first PRE suppression rows
    const unsigned long long* src = &g_sup[b][0][0];
    unsigned long long* dst = &ssup[0][0];
    for (int i = tid; i < PRE * NW; i += 256) dst[i] = src[i];
    __syncthreads();

    if (warp == 0) {
        unsigned long long remv = s_remv[lane];
        int cnt = 0, i = 0;
        while (i < KTOP && cnt < NDET) {
            int w = i >> 6;
            unsigned long long rw    = __shfl_sync(0xffffffffu, remv, w);
            unsigned long long avail = ~rw & (~0ull << (i & 63));
            if (avail == 0ull) { i = (w + 1) << 6; continue; }
            int bit = __ffsll((long long)avail) - 1;
            i = (w << 6) | bit;
            if (lane == 0) kept[cnt] = i;
            cnt++;
            remv |= (i < PRE) ? ssup[i][lane] : g_sup[b][i][lane];
            i++;
        }
        if (lane == 0) s_cnt = cnt;
    }
    __syncthreads();

    int cnt = s_cnt;
    for (int s = tid; s < NDET; s += 256) {
        float b0 = 0.f, b1 = 0.f, b2 = 0.f, b3 = 0.f, sv = 0.f, lv = 0.f;
        if (s < cnt) {
            int k = kept[s];
            b0 = g_box[b][k][0]; b1 = g_box[b][k][1];
            b2 = g_box[b][k][2]; b3 = g_box[b][k][3];
            sv = g_val[b][k];
            lv = (float)g_lab[b][k];
        }
        float* ob = out + (size_t)b * NDET * 4 + s * 4;
        ob[0] = b0; ob[1] = b1; ob[2] = b2; ob[3] = b3;
        out[NIMG * NDET * 4 + b * NDET + s] = sv;           // scores block
        out[NIMG * NDET * 5 + b * NDET + s] = lv;           // labels block
    }

    if (tid == 0) g_maxc[b] = 0u;                // reset for next replay
}

// ---------------- launcher ---------------------------------------------------
extern "C" void kernel_launch(void* const* d_in, const int* in_sizes, int n_in,
                              void* d_out, int out_size) {
    const float* logits = (const float*)d_in[0];   // [8,8000,81]
    const float* deltas = (const float*)d_in[1];   // [8,8000,324]
    const float* props  = (const float*)d_in[2];   // [8,8000,4]
    float* out = (float*)d_out;                    // [boxes|scores|labels] f32

    score_kernel<<<dim3(NPROP / 8, NIMG), 256>>>(logits, deltas, props);
    sort_kernel<<<NIMG, 1024>>>();
    gather_kernel<<<dim3(KTOP / 256, NIMG), 256>>>(deltas, props);
    sup_kernel<<<dim3(KTOP / 32, NIMG), 1024>>>();
    scan_kernel<<<NIMG, 256>>>(out);
}

// round 6
// speedup vs baseline: 4.9973x; 2.0442x over previous
#include <cuda_runtime.h>
#include <cstdint>

#define NIMG  8
#define NPROP 8000
#define NCLS  80
#define NLOG  81
#define KTOP  2048
#define CAP   4096
#define NDET  100
#define NW    32   // 2048 / 64 bits
#define PRE   160  // suppression rows preloaded into smem in scan

#define SCORE_THRE 0.15f
#define MIN_AREA   0.1f
#define NMS_TH     0.5f

// ---------------- scratch (device globals; no allocations allowed) ----------
__device__ int                 g_cnt[NIMG];
__device__ int                 g_ncand[NIMG];
__device__ unsigned long long  g_keys[NIMG][CAP];
__device__ float               g_box[NIMG][KTOP][4];
__device__ float               g_val[NIMG][KTOP];
__device__ int                 g_lab[NIMG][KTOP];
__device__ unsigned int        g_maxc[NIMG];                 // float bits (>=0)
__device__ unsigned long long  g_sup[NIMG][KTOP][NW];

// ---------------- kernel 1: softmax + decode + filter + append --------------
__global__ void score_kernel(const float* __restrict__ logits,
                             const float* __restrict__ deltas,
                             const float* __restrict__ props) {
    int b    = blockIdx.y;
    int p    = blockIdx.x * (blockDim.x >> 5) + (threadIdx.x >> 5);
    int lane = threadIdx.x & 31;
    if (p >= NPROP) return;

    const float* lg = logits + (size_t)(b * NPROP + p) * NLOG;
    float v0 = lg[lane];
    float v1 = lg[32 + lane];
    float v2 = (lane < NLOG - 64) ? lg[64 + lane] : -3.4e38f;

    float mx = fmaxf(fmaxf(v0, v1), v2);
#pragma unroll
    for (int o = 16; o; o >>= 1) mx = fmaxf(mx, __shfl_xor_sync(0xffffffffu, mx, o));

    float e0 = expf(v0 - mx);
    float e1 = expf(v1 - mx);
    float e2 = (lane < NLOG - 64) ? expf(v2 - mx) : 0.0f;
    float s  = e0 + e1 + e2;
#pragma unroll
    for (int o = 16; o; o >>= 1) s += __shfl_xor_sync(0xffffffffu, s, o);

    float inv_s = (lane == 0) ? (1.0f / s) : 0.0f;   // one IEEE rcp per warp
    inv_s = __shfl_sync(0xffffffffu, inv_s, 0);

    const float* pr = props + (size_t)(b * NPROP + p) * 4;
    float ax0 = pr[0], ay0 = pr[1], ax1 = pr[2], ay1 = pr[3];
    float wa  = ax1 - ax0, ha = ay1 - ay0;

    const float* dl = deltas + (size_t)(b * NPROP + p) * (4 * NLOG);

    float es[3] = { e0, e1, e2 };
#pragma unroll
    for (int t = 0; t < 3; t++) {
        int cls = lane + 32 * t;                 // softmax class index
        if (cls >= 1 && cls < NLOG) {
            float sc = es[t] * inv_s;
            if (sc > SCORE_THRE) {
                float dw = dl[4 * cls + 2];
                float dh = dl[4 * cls + 3];
                float w  = __expf(dw) * wa;      // area test only
                float h  = __expf(dh) * ha;
                float area = h * w;
                if (area > MIN_AREA) {
                    int idx = p * NCLS + (cls - 1);
                    int pos = atomicAdd(&g_cnt[b], 1);
                    if (pos < CAP) {
                        unsigned long long key =
                            ((unsigned long long)__float_as_uint(sc) << 32) |
                            (unsigned)(0xFFFFFFFFu - (unsigned)idx);
                        g_keys[b][pos] = key;
                    }
                }
            }
        }
    }
}

// ---------------- kernel 2: per-image bitonic sort, dynamic size ------------
__global__ void sort_kernel() {
    __shared__ unsigned long long sk[CAP];
    int b = blockIdx.x;
    int t = threadIdx.x;
    int cnt = g_cnt[b];
    if (cnt > CAP) cnt = CAP;

    int npow = 1024;
    while (npow < cnt) npow <<= 1;               // <= CAP

    for (int i = t; i < npow; i += 1024)
        sk[i] = (i < cnt) ? g_keys[b][i] : 0ull;
    __syncthreads();
    if (t == 0) {
        g_cnt[b]   = 0;                          // reset for next replay
        g_ncand[b] = (cnt < KTOP) ? cnt : KTOP;  // real candidate count
    }

    for (int k = 2; k <= npow; k <<= 1) {
        for (int j = k >> 1; j; j >>= 1) {
            for (int idx = t; idx < (npow >> 1); idx += 1024) {
                int low = idx & (j - 1);
                int i   = ((idx ^ low) << 1) | low;
                int ixj = i | j;
                unsigned long long a = sk[i], c = sk[ixj];
                bool up = ((i & k) == 0);
                if ((a > c) == up) { sk[i] = c; sk[ixj] = a; }
            }
            __syncthreads();
        }
    }
    for (int r = t; r < KTOP; r += 1024)
        g_keys[b][r] = (r < npow) ? sk[npow - 1 - r] : 0ull;
}

// ---------------- kernel 3: gather top-2048, re-decode, max_coord -----------
__global__ void gather_kernel(const float* __restrict__ deltas,
                              const float* __restrict__ props) {
    int b = blockIdx.y;
    int r = blockIdx.x * blockDim.x + threadIdx.x;
    if (r >= KTOP) return;

    unsigned long long key = g_keys[b][r];
    if (key == 0ull) {
        g_val[b][r] = -1.0f;
        g_lab[b][r] = 0;
        g_box[b][r][0] = 0.f; g_box[b][r][1] = 0.f;
        g_box[b][r][2] = 0.f; g_box[b][r][3] = 0.f;
        return;
    }
    float    sc  = __uint_as_float((unsigned)(key >> 32));
    unsigned idx = 0xFFFFFFFFu - (unsigned)(key & 0xFFFFFFFFull);
    int p   = (int)(idx / NCLS);
    int j   = (int)(idx - (unsigned)p * NCLS);
    int cls = j + 1;

    const float* pr = props + (size_t)(b * NPROP + p) * 4;
    float ax0 = pr[0], ay0 = pr[1], ax1 = pr[2], ay1 = pr[3];
    float wa  = ax1 - ax0, ha = ay1 - ay0;
    float cxa = ax0 + 0.5f * wa, cya = ay0 + 0.5f * ha;

    const float* dl = deltas + (size_t)(b * NPROP + p) * (4 * NLOG);
    float dx = dl[4 * cls + 0];
    float dy = dl[4 * cls + 1];
    float dw = dl[4 * cls + 2];
    float dh = dl[4 * cls + 3];
    float cx = dx * wa + cxa;
    float cy = dy * ha + cya;
    float w  = expf(dw) * wa;
    float h  = expf(dh) * ha;
    float bx0 = cx - 0.5f * w, by0 = cy - 0.5f * h;
    float bx1 = cx + 0.5f * w, by1 = cy + 0.5f * h;

    g_box[b][r][0] = bx0; g_box[b][r][1] = by0;
    g_box[b][r][2] = bx1; g_box[b][r][3] = by1;
    g_val[b][r] = sc;
    g_lab[b][r] = cls;

    float m = fmaxf(fmaxf(bx0, bx1), fmaxf(by0, by1));
    m = fmaxf(m, 0.0f);
    atomicMax(&g_maxc[b], __float_as_uint(m));
}

// ---------------- kernel 4: suppression bitmask, ncand-bounded, div-free ----
__global__ void sup_kernel() {
    __shared__ float4 sbox[KTOP];    // 32 KB
    __shared__ float  sarea[KTOP];   //  8 KB
    int b     = blockIdx.y;
    int ncand = g_ncand[b];
    int i0    = blockIdx.x * 32;
    if (i0 >= ncand) return;                     // rows never kept -> never read

    float mc = __uint_as_float(g_maxc[b]) + 1.0f;

    for (int i = threadIdx.x; i < ncand; i += blockDim.x) {
        float off = (float)g_lab[b][i] * mc;
        float x0 = g_box[b][i][0] + off;
        float y0 = g_box[b][i][1] + off;
        float x1 = g_box[b][i][2] + off;
        float y1 = g_box[b][i][3] + off;
        sbox[i]  = make_float4(x0, y0, x1, y1);
        sarea[i] = (x1 - x0) * (y1 - y0);
    }
    __syncthreads();

    int warp = threadIdx.x >> 5;
    int lane = threadIdx.x & 31;
    int i = i0 + warp;
    if (i >= ncand) return;                      // warp-uniform exit

    float4 A  = sbox[i];
    float aar = sarea[i];

    int tmax = (ncand + 31) >> 5;
    unsigned long long myw = 0ull;
    for (int t = (i >> 5); t < tmax; t++) {
        int j = t * 32 + lane;
        bool hit = false;
        if (j > i && j < ncand) {
            float4 B = sbox[j];
            float lx = fmaxf(A.x, B.x);
            float ly = fmaxf(A.y, B.y);
            float rx = fminf(A.z, B.z);
            float ry = fminf(A.w, B.w);
            float iw = fmaxf(rx - lx, 0.0f);
            float ih = fmaxf(ry - ly, 0.0f);
            float inter = iw * ih;
            // iou > TH  <=>  inter > TH*(a+b-inter+eps)   (denominator > 0)
            hit = inter > NMS_TH * (aar + sarea[j] - inter + 1e-9f);
        }
        unsigned bal = __ballot_sync(0xffffffffu, hit);
        if (lane == (t >> 1))
            myw |= ((unsigned long long)bal) << ((t & 1) * 32);
    }
    g_sup[b][i][lane] = myw;                     // full 256B row overwrite
}

// ---------------- kernel 5: greedy NMS skip-scan (smem) + output ------------
__global__ void scan_kernel(float* __restrict__ out) {
    __shared__ unsigned long long ssup[PRE][NW];   // 40 KB
    __shared__ unsigned long long s_remv[NW];
    __shared__ int kept[NDET];
    __shared__ int s_cnt;
    int b    = blockIdx.x;
    int tid  = threadIdx.x;
    int warp = tid >> 5;
    int lane = tid & 31;

    for (int wd = warp; wd < NW; wd += 8) {
        unsigned lo = __ballot_sync(0xffffffffu, g_val[b][wd * 64 + lane]      <= 0.0f);
        unsigned hi = __ballot_sync(0xffffffffu, g_val[b][wd * 64 + 32 + lane] <= 0.0f);
        if (lane == 0)
            s_remv[wd] = (unsigned long long)lo | ((unsigned long long)hi << 32);
    }
    const unsigned long long* src = &g_sup[b][0][0];
    unsigned long long* dst = &ssup[0][0];
    for (int i = tid; i < PRE * NW; i += 256) dst[i] = src[i];
    __syncthreads();

    if (warp == 0) {
        unsigned long long remv = s_remv[lane];
        int cnt = 0, i = 0;
        while (i < KTOP && cnt < NDET) {
            int w = i >> 6;
            unsigned long long rw    = __shfl_sync(0xffffffffu, remv, w);
            unsigned long long avail = ~rw & (~0ull << (i & 63));
            if (avail == 0ull) { i = (w + 1) << 6; continue; }
            int bit = __ffsll((long long)avail) - 1;
            i = (w << 6) | bit;
            if (lane == 0) kept[cnt] = i;
            cnt++;
            remv |= (i < PRE) ? ssup[i][lane] : g_sup[b][i][lane];
            i++;
        }
        if (lane == 0) s_cnt = cnt;
    }
    __syncthreads();

    int cnt = s_cnt;
    for (int s = tid; s < NDET; s += 256) {
        float b0 = 0.f, b1 = 0.f, b2 = 0.f, b3 = 0.f, sv = 0.f, lv = 0.f;
        if (s < cnt) {
            int k = kept[s];
            b0 = g_box[b][k][0]; b1 = g_box[b][k][1];
            b2 = g_box[b][k][2]; b3 = g_box[b][k][3];
            sv = g_val[b][k];
            lv = (float)g_lab[b][k];
        }
        float* ob = out + (size_t)b * NDET * 4 + s * 4;
        ob[0] = b0; ob[1] = b1; ob[2] = b2; ob[3] = b3;
        out[NIMG * NDET * 4 + b * NDET + s] = sv;
        out[NIMG * NDET * 5 + b * NDET + s] = lv;
    }

    if (tid == 0) g_maxc[b] = 0u;                // reset for next replay
}

// ---------------- launcher ---------------------------------------------------
extern "C" void kernel_launch(void* const* d_in, const int* in_sizes, int n_in,
                              void* d_out, int out_size) {
    const float* logits = (const float*)d_in[0];   // [8,8000,81]
    const float* deltas = (const float*)d_in[1];   // [8,8000,324]
    const float* props  = (const float*)d_in[2];   // [8,8000,4]
    float* out = (float*)d_out;                    // [boxes|scores|labels] f32

    score_kernel<<<dim3(NPROP / 8, NIMG), 256>>>(logits, deltas, props);
    sort_kernel<<<NIMG, 1024>>>();
    gather_kernel<<<dim3(KTOP / 256, NIMG), 256>>>(deltas, props);
    sup_kernel<<<dim3(KTOP / 32, NIMG), 1024>>>();
    scan_kernel<<<NIMG, 256>>>(out);
}